// round 16
// baseline (speedup 1.0000x reference)
#include <cuda_runtime.h>
#include <cuda_fp16.h>
#include <math.h>
#include <stdint.h>

// Problem constants
#define BSZ   64
#define HDIM  4096
#define IDIM  14336
#define NLUT  4096
#define WSCALE 0.02f

#define NTHREADS 256
#define BK 64                  // K per tile (64 fp16 = 128B row)
#define TM 128                 // weight rows per CTA tile
#define SKG 4                  // split-K gate/up over HDIM
#define KSLICE_G (HDIM / SKG)  // 1024 -> 16 tiles
#define NT_G (KSLICE_G / BK)
#define SKD 28                 // split-K down over IDIM
#define KSLICE_D (IDIM / SKD)  // 512 -> 8 tiles
#define NT_D (KSLICE_D / BK)

#define SW128(o) ((o) ^ ((((uint32_t)(o)) >> 3) & 0x70))

// ---- scratch (static device arrays; no allocations) ----
__device__ __half d_xgh[BSZ * HDIM];                     // fp16(x * gsr * WSCALE)
__device__ __half d_xuh[BSZ * HDIM];                     // fp16(x * usr * WSCALE)
__device__ __half d_lgh[NLUT];                           // fp16 lut_gate
__device__ __half d_luh[NLUT];                           // fp16 lut_up
__device__ __half d_ldh[NLUT];                           // fp16(lut_down * WSCALE)
__device__ float  d_gpart[(size_t)SKG * IDIM * BSZ];     // [slice][i][b]
__device__ float  d_upart[(size_t)SKG * IDIM * BSZ];
__device__ float  d_dpart[(size_t)SKD * HDIM * BSZ];     // [slice][h][b]
__device__ __half d_hdh[BSZ * IDIM];                     // hidden fp16 [b][i]

// ---------------- PTX helpers (baseline ISA only) ----------------
__device__ __forceinline__ uint32_t smem_u32(const void* p) {
    uint32_t a;
    asm("{ .reg .u64 t; cvta.to.shared.u64 t, %1; cvt.u32.u64 %0, t; }" : "=r"(a) : "l"(p));
    return a;
}

__device__ __forceinline__ void ldmx4(uint32_t* r, uint32_t addr) {
    asm volatile("ldmatrix.sync.aligned.m8n8.x4.shared.b16 {%0,%1,%2,%3}, [%4];"
                 : "=r"(r[0]), "=r"(r[1]), "=r"(r[2]), "=r"(r[3]) : "r"(addr));
}

__device__ __forceinline__ void mma16816(float* c, const uint32_t* a,
                                         uint32_t b0, uint32_t b1) {
    asm volatile(
        "mma.sync.aligned.m16n8k16.row.col.f32.f16.f16.f32 "
        "{%0,%1,%2,%3}, {%4,%5,%6,%7}, {%8,%9}, {%0,%1,%2,%3};"
        : "+f"(c[0]), "+f"(c[1]), "+f"(c[2]), "+f"(c[3])
        : "r"(a[0]), "r"(a[1]), "r"(a[2]), "r"(a[3]), "r"(b0), "r"(b1));
}

// ---------------- prep ----------------
__global__ void prep_kernel(const float* __restrict__ x,
                            const float* __restrict__ gsr,
                            const float* __restrict__ usr,
                            const float* __restrict__ lg,
                            const float* __restrict__ lu,
                            const float* __restrict__ ld) {
    int idx = blockIdx.x * blockDim.x + threadIdx.x;
    if (idx < BSZ * HDIM) {
        int h = idx & (HDIM - 1);
        float xv = x[idx];
        d_xgh[idx] = __float2half(xv * gsr[h] * WSCALE);
        d_xuh[idx] = __float2half(xv * usr[h] * WSCALE);
    }
    if (idx < NLUT) {
        d_lgh[idx] = __float2half(lg[idx]);
        d_luh[idx] = __float2half(lu[idx]);
        d_ldh[idx] = __float2half(ld[idx] * WSCALE);  // fold WSCALE into down LUT
    }
}

// ---------------- tile loaders ----------------
// dequant: 128 rows x 64 codes -> fp16 SW128 tile (1024 16B chunks, 4/thread)
__device__ __forceinline__ void dequant_tile(const int* __restrict__ walks,
                                             int rowStride, int row0, int k0,
                                             const __half* __restrict__ lut,
                                             char* sA, int tid) {
#pragma unroll
    for (int g = 0; g < 4; ++g) {
        int chunk = tid + g * NTHREADS;
        int row = chunk >> 3;
        int cc = chunk & 7;
        const int4* p = (const int4*)(walks + (size_t)(row0 + row) * rowStride + k0 + cc * 8);
        int4 a = p[0], b = p[1];
        __half2 h0 = __halves2half2(lut[a.x], lut[a.y]);
        __half2 h1 = __halves2half2(lut[a.z], lut[a.w]);
        __half2 h2 = __halves2half2(lut[b.x], lut[b.y]);
        __half2 h3 = __halves2half2(lut[b.z], lut[b.w]);
        uint32_t off = row * 128 + cc * 16;
        uint4 v;
        v.x = *(uint32_t*)&h0; v.y = *(uint32_t*)&h1;
        v.z = *(uint32_t*)&h2; v.w = *(uint32_t*)&h3;
        *(uint4*)(sA + SW128(off)) = v;
    }
}

// X tile: 64 rows x 64 fp16 -> SW128 (512 chunks, 2/thread)
__device__ __forceinline__ void xload_tile(const __half* __restrict__ xsrc,
                                           int rowStride, int k0, char* sX, int tid) {
#pragma unroll
    for (int it = 0; it < 2; ++it) {
        int idx = tid + it * NTHREADS;
        int row = idx >> 3;
        int c = idx & 7;
        uint4 v = *(const uint4*)(xsrc + (size_t)row * rowStride + k0 + c * 8);
        uint32_t off = row * 128 + c * 16;
        *(uint4*)(sX + SW128(off)) = v;
    }
}

// ---------------- core GEMM tile compute ----------------
// acc[mi][nj][4]; Ab[2], Bb[2] are swizzled lane base addresses; addr = base ^ (ks<<5)
__device__ __forceinline__ void tile_mma(const uint32_t* Ab, const uint32_t* Bb,
                                         float acc[2][4][4]) {
#pragma unroll
    for (int ks = 0; ks < 4; ++ks) {
        uint32_t x = (uint32_t)(ks << 5);
        uint32_t a[2][4];
        ldmx4(a[0], Ab[0] ^ x);
        ldmx4(a[1], Ab[1] ^ x);
#pragma unroll
        for (int nb = 0; nb < 2; ++nb) {
            uint32_t r[4];
            ldmx4(r, Bb[nb] ^ x);
#pragma unroll
            for (int mi = 0; mi < 2; ++mi) {
                mma16816(acc[mi][2 * nb + 0], a[mi], r[0], r[1]);
                mma16816(acc[mi][2 * nb + 1], a[mi], r[2], r[3]);
            }
        }
    }
}

// lane geometry -> swizzled base addresses
__device__ __forceinline__ void make_bases(uint32_t sAb, uint32_t sXb,
                                           int mw, int nw, int lane,
                                           uint32_t* Ab, uint32_t* Bb) {
#pragma unroll
    for (int mi = 0; mi < 2; ++mi) {
        int row = mw + mi * 16 + (lane & 15);
        uint32_t off = (uint32_t)(row * 128 + (lane >> 4) * 16);
        Ab[mi] = sAb + SW128(off);
    }
#pragma unroll
    for (int nb = 0; nb < 2; ++nb) {
        int row = nw + nb * 16 + (lane & 7) + ((lane >> 4) << 3);
        uint32_t off = (uint32_t)(row * 128 + ((lane >> 3) & 1) * 16);
        Bb[nb] = sXb + SW128(off);
    }
}

// epilogue: write C fragments to partials laid out [row][b] (row-major, 64 b cols)
__device__ __forceinline__ void store_parts(float* part, int r0, int mw, int nw,
                                            int lane, float acc[2][4][4]) {
#pragma unroll
    for (int mi = 0; mi < 2; ++mi) {
        int row = r0 + mw + mi * 16 + (lane >> 2);
#pragma unroll
        for (int nj = 0; nj < 4; ++nj) {
            int bc = nw + nj * 8 + (lane & 3) * 2;
            float2 v0 = {acc[mi][nj][0], acc[mi][nj][1]};
            float2 v1 = {acc[mi][nj][2], acc[mi][nj][3]};
            *(float2*)(part + (size_t)row * BSZ + bc) = v0;
            *(float2*)(part + (size_t)(row + 8) * BSZ + bc) = v1;
        }
    }
}

// ---------------- gate/up GEMM (blockIdx.z: 0=gate, 1=up) ----------------
__global__ __launch_bounds__(NTHREADS, 3)
void gateup_kernel(const int* __restrict__ gwalks, const int* __restrict__ uwalks) {
    __shared__ __half sLut[NLUT];
    __shared__ __align__(128) char sA[TM * 128];
    __shared__ __align__(128) char sX[BSZ * 128];

    const int tid = threadIdx.x;
    const int lane = tid & 31;
    const int wid = tid >> 5;
    const int z = blockIdx.z;

    const int* walks = z ? uwalks : gwalks;
    const __half* lutg = z ? d_luh : d_lgh;
    const __half* xsrc = z ? d_xuh : d_xgh;

    {   // LUT -> smem
        const uint4* l4 = (const uint4*)lutg;
        uint4* s4 = (uint4*)sLut;
        s4[tid] = l4[tid];
        s4[tid + NTHREADS] = l4[tid + NTHREADS];
    }

    const int mw = (wid & 3) * 32;
    const int nw = (wid >> 2) * 32;
    uint32_t Ab[2], Bb[2];
    make_bases(smem_u32(sA), smem_u32(sX), mw, nw, lane, Ab, Bb);

    float acc[2][4][4];
#pragma unroll
    for (int mi = 0; mi < 2; ++mi)
#pragma unroll
        for (int nj = 0; nj < 4; ++nj)
#pragma unroll
            for (int q = 0; q < 4; ++q) acc[mi][nj][q] = 0.f;

    const int i0 = blockIdx.x * TM;
    const int kBeg = blockIdx.y * KSLICE_G;

    for (int t = 0; t < NT_G; ++t) {
        const int k0 = kBeg + t * BK;
        __syncthreads();                       // previous tile fully consumed
        dequant_tile(walks, HDIM, i0, k0, sLut, sA, tid);
        xload_tile(xsrc, HDIM, k0, sX, tid);
        __syncthreads();
        tile_mma(Ab, Bb, acc);
    }

    float* part = (z ? d_upart : d_gpart) + (size_t)blockIdx.y * ((size_t)IDIM * BSZ);
    store_parts(part, i0, mw, nw, lane, acc);
}

// ---------------- reduce gate/up partials + silu*mul -> fp16 hidden ----------------
__global__ void hd_kernel(const float* __restrict__ gsl,
                          const float* __restrict__ usl,
                          const float* __restrict__ dsr) {
    int t = blockIdx.x * blockDim.x + threadIdx.x;   // IDIM*16 threads
    int i = t >> 4;
    int bq = (t & 15) * 4;
    size_t off = (size_t)i * BSZ + bq;

    float4 g = {0.f, 0.f, 0.f, 0.f}, u = {0.f, 0.f, 0.f, 0.f};
#pragma unroll
    for (int s = 0; s < SKG; ++s) {
        size_t po = (size_t)s * ((size_t)IDIM * BSZ) + off;
        float4 gv = *(const float4*)(d_gpart + po);
        float4 uv = *(const float4*)(d_upart + po);
        g.x += gv.x; g.y += gv.y; g.z += gv.z; g.w += gv.w;
        u.x += uv.x; u.y += uv.y; u.z += uv.z; u.w += uv.w;
    }
    float gl = gsl[i], ul = usl[i], dr = dsr[i];
    float gg[4] = {g.x * gl, g.y * gl, g.z * gl, g.w * gl};
    float uu[4] = {u.x * ul, u.y * ul, u.z * ul, u.w * ul};
#pragma unroll
    for (int j = 0; j < 4; ++j) {
        float sg = gg[j] / (1.0f + __expf(-gg[j]));
        d_hdh[(size_t)(bq + j) * IDIM + i] = __float2half(sg * uu[j] * dr);
    }
}

// ---------------- down GEMM ----------------
__global__ __launch_bounds__(NTHREADS, 3)
void down_kernel(const int* __restrict__ walks) {
    __shared__ __half sLut[NLUT];
    __shared__ __align__(128) char sA[TM * 128];
    __shared__ __align__(128) char sX[BSZ * 128];

    const int tid = threadIdx.x;
    const int lane = tid & 31;
    const int wid = tid >> 5;

    {
        const uint4* l4 = (const uint4*)d_ldh;
        uint4* s4 = (uint4*)sLut;
        s4[tid] = l4[tid];
        s4[tid + NTHREADS] = l4[tid + NTHREADS];
    }

    const int mw = (wid & 3) * 32;
    const int nw = (wid >> 2) * 32;
    uint32_t Ab[2], Bb[2];
    make_bases(smem_u32(sA), smem_u32(sX), mw, nw, lane, Ab, Bb);

    float acc[2][4][4];
#pragma unroll
    for (int mi = 0; mi < 2; ++mi)
#pragma unroll
        for (int nj = 0; nj < 4; ++nj)
#pragma unroll
            for (int q = 0; q < 4; ++q) acc[mi][nj][q] = 0.f;

    const int h0 = blockIdx.x * TM;
    const int kBeg = blockIdx.y * KSLICE_D;

    for (int t = 0; t < NT_D; ++t) {
        const int k0 = kBeg + t * BK;
        __syncthreads();
        dequant_tile(walks, IDIM, h0, k0, sLut, sA, tid);
        xload_tile(d_hdh, IDIM, k0, sX, tid);
        __syncthreads();
        tile_mma(Ab, Bb, acc);
    }

    float* part = d_dpart + (size_t)blockIdx.y * ((size_t)HDIM * BSZ);
    store_parts(part, h0, mw, nw, lane, acc);
}

// ---------------- reduce down partials -> out ----------------
__global__ void dreduce_kernel(const float* __restrict__ dsl, float* __restrict__ out) {
    int t = blockIdx.x * blockDim.x + threadIdx.x;   // HDIM*16 threads
    int h = t >> 4;
    int bq = (t & 15) * 4;
    size_t off = (size_t)h * BSZ + bq;

    float4 a = {0.f, 0.f, 0.f, 0.f};
#pragma unroll
    for (int s = 0; s < SKD; ++s) {
        float4 v = *(const float4*)(d_dpart + (size_t)s * ((size_t)HDIM * BSZ) + off);
        a.x += v.x; a.y += v.y; a.z += v.z; a.w += v.w;
    }
    float sc = dsl[h];
    out[(size_t)(bq + 0) * HDIM + h] = a.x * sc;
    out[(size_t)(bq + 1) * HDIM + h] = a.y * sc;
    out[(size_t)(bq + 2) * HDIM + h] = a.z * sc;
    out[(size_t)(bq + 3) * HDIM + h] = a.w * sc;
}

// ---------------- launch ----------------
extern "C" void kernel_launch(void* const* d_in, const int* in_sizes, int n_in,
                              void* d_out, int out_size) {
    const float* x        = (const float*)d_in[0];
    const float* lut_gate = (const float*)d_in[1];
    const float* lut_up   = (const float*)d_in[2];
    const float* lut_down = (const float*)d_in[3];
    const int*   gwalks   = (const int*)d_in[4];
    const int*   uwalks   = (const int*)d_in[5];
    const int*   dwalks   = (const int*)d_in[6];
    const float* gsl      = (const float*)d_in[7];
    // gsr = d_in[8]
    const float* usl      = (const float*)d_in[9];
    // usr = d_in[10]
    const float* dsl      = (const float*)d_in[11];
    const float* dsr      = (const float*)d_in[12];
    const float* gsr      = (const float*)d_in[8];
    const float* usr      = (const float*)d_in[10];
    float* out = (float*)d_out;

    prep_kernel<<<(BSZ * HDIM + 255) / 256, 256>>>(x, gsr, usr, lut_gate, lut_up, lut_down);
    gateup_kernel<<<dim3(IDIM / TM, SKG, 2), NTHREADS>>>(gwalks, uwalks);
    hd_kernel<<<(IDIM * 16) / 256, 256>>>(gsl, usl, dsr);
    down_kernel<<<dim3(HDIM / TM, SKD), NTHREADS>>>(dwalks);
    dreduce_kernel<<<(HDIM * 16) / 256, 256>>>(dsl, out);
}

// round 17
// speedup vs baseline: 1.0078x; 1.0078x over previous
#include <cuda_runtime.h>
#include <cuda_fp16.h>
#include <math.h>
#include <stdint.h>

// Problem constants
#define BSZ   64
#define HDIM  4096
#define IDIM  14336
#define NLUT  4096
#define WSCALE 0.02f

#define NTHREADS 256
#define BK 64                  // K per tile (64 fp16 = 128B row)
#define TM 128                 // weight rows per CTA tile
#define SKG 4                  // split-K gate/up over HDIM
#define KSLICE_G (HDIM / SKG)  // 1024 -> 16 tiles
#define NT_G (KSLICE_G / BK)
#define SKD 28                 // split-K down over IDIM
#define KSLICE_D (IDIM / SKD)  // 512 -> 8 tiles
#define NT_D (KSLICE_D / BK)

#define SW128(o) ((o) ^ ((((uint32_t)(o)) >> 3) & 0x70))

// ---- scratch (static device arrays; no allocations) ----
__device__ __half d_xgh[BSZ * HDIM];                     // fp16(x * gsr * WSCALE)
__device__ __half d_xuh[BSZ * HDIM];                     // fp16(x * usr * WSCALE)
__device__ __half d_lgh[NLUT];                           // fp16 lut_gate
__device__ __half d_luh[NLUT];                           // fp16 lut_up
__device__ __half d_ldh[NLUT];                           // fp16(lut_down * WSCALE)
__device__ float  d_gpart[(size_t)SKG * IDIM * BSZ];     // [slice][i][b]
__device__ float  d_upart[(size_t)SKG * IDIM * BSZ];
__device__ float  d_dpart[(size_t)SKD * HDIM * BSZ];     // [slice][h][b]
__device__ __half d_hdh[BSZ * IDIM];                     // hidden fp16 [b][i]

// ---------------- PTX helpers (baseline ISA only) ----------------
__device__ __forceinline__ uint32_t smem_u32(const void* p) {
    uint32_t a;
    asm("{ .reg .u64 t; cvta.to.shared.u64 t, %1; cvt.u32.u64 %0, t; }" : "=r"(a) : "l"(p));
    return a;
}

__device__ __forceinline__ void ldmx4(uint32_t* r, uint32_t addr) {
    asm volatile("ldmatrix.sync.aligned.m8n8.x4.shared.b16 {%0,%1,%2,%3}, [%4];"
                 : "=r"(r[0]), "=r"(r[1]), "=r"(r[2]), "=r"(r[3]) : "r"(addr));
}

__device__ __forceinline__ void mma16816(float* c, const uint32_t* a,
                                         uint32_t b0, uint32_t b1) {
    asm volatile(
        "mma.sync.aligned.m16n8k16.row.col.f32.f16.f16.f32 "
        "{%0,%1,%2,%3}, {%4,%5,%6,%7}, {%8,%9}, {%0,%1,%2,%3};"
        : "+f"(c[0]), "+f"(c[1]), "+f"(c[2]), "+f"(c[3])
        : "r"(a[0]), "r"(a[1]), "r"(a[2]), "r"(a[3]), "r"(b0), "r"(b1));
}

// ---------------- prep ----------------
__global__ void prep_kernel(const float* __restrict__ x,
                            const float* __restrict__ gsr,
                            const float* __restrict__ usr,
                            const float* __restrict__ lg,
                            const float* __restrict__ lu,
                            const float* __restrict__ ld) {
    int idx = blockIdx.x * blockDim.x + threadIdx.x;
    if (idx < BSZ * HDIM) {
        int h = idx & (HDIM - 1);
        float xv = x[idx];
        d_xgh[idx] = __float2half(xv * gsr[h] * WSCALE);
        d_xuh[idx] = __float2half(xv * usr[h] * WSCALE);
    }
    if (idx < NLUT) {
        d_lgh[idx] = __float2half(lg[idx]);
        d_luh[idx] = __float2half(lu[idx]);
        d_ldh[idx] = __float2half(ld[idx] * WSCALE);  // fold WSCALE into down LUT
    }
}

// ---------------- tile loaders ----------------
// dequant: 128 rows x 64 codes -> fp16 SW128 tile (1024 16B chunks, 4/thread)
__device__ __forceinline__ void dequant_tile(const int* __restrict__ walks,
                                             int rowStride, int row0, int k0,
                                             const __half* __restrict__ lut,
                                             char* sA, int tid) {
#pragma unroll
    for (int g = 0; g < 4; ++g) {
        int chunk = tid + g * NTHREADS;
        int row = chunk >> 3;
        int cc = chunk & 7;
        const int4* p = (const int4*)(walks + (size_t)(row0 + row) * rowStride + k0 + cc * 8);
        int4 a = p[0], b = p[1];
        __half2 h0 = __halves2half2(lut[a.x], lut[a.y]);
        __half2 h1 = __halves2half2(lut[a.z], lut[a.w]);
        __half2 h2 = __halves2half2(lut[b.x], lut[b.y]);
        __half2 h3 = __halves2half2(lut[b.z], lut[b.w]);
        uint32_t off = row * 128 + cc * 16;
        uint4 v;
        v.x = *(uint32_t*)&h0; v.y = *(uint32_t*)&h1;
        v.z = *(uint32_t*)&h2; v.w = *(uint32_t*)&h3;
        *(uint4*)(sA + SW128(off)) = v;
    }
}

// X tile: 64 rows x 64 fp16 -> SW128 (512 chunks, 2/thread)
__device__ __forceinline__ void xload_tile(const __half* __restrict__ xsrc,
                                           int rowStride, int k0, char* sX, int tid) {
#pragma unroll
    for (int it = 0; it < 2; ++it) {
        int idx = tid + it * NTHREADS;
        int row = idx >> 3;
        int c = idx & 7;
        uint4 v = *(const uint4*)(xsrc + (size_t)row * rowStride + k0 + c * 8);
        uint32_t off = row * 128 + c * 16;
        *(uint4*)(sX + SW128(off)) = v;
    }
}

// ---------------- core GEMM tile compute ----------------
// acc[mi][nj][4]; Ab[2], Bb[2] are swizzled lane base addresses; addr = base ^ (ks<<5)
__device__ __forceinline__ void tile_mma(const uint32_t* Ab, const uint32_t* Bb,
                                         float acc[2][4][4]) {
#pragma unroll
    for (int ks = 0; ks < 4; ++ks) {
        uint32_t x = (uint32_t)(ks << 5);
        uint32_t a[2][4];
        ldmx4(a[0], Ab[0] ^ x);
        ldmx4(a[1], Ab[1] ^ x);
#pragma unroll
        for (int nb = 0; nb < 2; ++nb) {
            uint32_t r[4];
            ldmx4(r, Bb[nb] ^ x);
#pragma unroll
            for (int mi = 0; mi < 2; ++mi) {
                mma16816(acc[mi][2 * nb + 0], a[mi], r[0], r[1]);
                mma16816(acc[mi][2 * nb + 1], a[mi], r[2], r[3]);
            }
        }
    }
}

// lane geometry -> swizzled base addresses
__device__ __forceinline__ void make_bases(uint32_t sAb, uint32_t sXb,
                                           int mw, int nw, int lane,
                                           uint32_t* Ab, uint32_t* Bb) {
#pragma unroll
    for (int mi = 0; mi < 2; ++mi) {
        int row = mw + mi * 16 + (lane & 15);
        uint32_t off = (uint32_t)(row * 128 + (lane >> 4) * 16);
        Ab[mi] = sAb + SW128(off);
    }
#pragma unroll
    for (int nb = 0; nb < 2; ++nb) {
        int row = nw + nb * 16 + (lane & 7) + ((lane >> 4) << 3);
        uint32_t off = (uint32_t)(row * 128 + ((lane >> 3) & 1) * 16);
        Bb[nb] = sXb + SW128(off);
    }
}

// epilogue: write C fragments to partials laid out [row][b] (row-major, 64 b cols)
__device__ __forceinline__ void store_parts(float* part, int r0, int mw, int nw,
                                            int lane, float acc[2][4][4]) {
#pragma unroll
    for (int mi = 0; mi < 2; ++mi) {
        int row = r0 + mw + mi * 16 + (lane >> 2);
#pragma unroll
        for (int nj = 0; nj < 4; ++nj) {
            int bc = nw + nj * 8 + (lane & 3) * 2;
            float2 v0 = {acc[mi][nj][0], acc[mi][nj][1]};
            float2 v1 = {acc[mi][nj][2], acc[mi][nj][3]};
            *(float2*)(part + (size_t)row * BSZ + bc) = v0;
            *(float2*)(part + (size_t)(row + 8) * BSZ + bc) = v1;
        }
    }
}

// ---------------- gate/up GEMM (blockIdx.z: 0=gate, 1=up) ----------------
__global__ __launch_bounds__(NTHREADS, 3)
void gateup_kernel(const int* __restrict__ gwalks, const int* __restrict__ uwalks) {
    __shared__ __half sLut[NLUT];
    __shared__ __align__(128) char sA[TM * 128];
    __shared__ __align__(128) char sX[BSZ * 128];

    const int tid = threadIdx.x;
    const int lane = tid & 31;
    const int wid = tid >> 5;
    const int z = blockIdx.z;

    const int* walks = z ? uwalks : gwalks;
    const __half* lutg = z ? d_luh : d_lgh;
    const __half* xsrc = z ? d_xuh : d_xgh;

    {   // LUT -> smem
        const uint4* l4 = (const uint4*)lutg;
        uint4* s4 = (uint4*)sLut;
        s4[tid] = l4[tid];
        s4[tid + NTHREADS] = l4[tid + NTHREADS];
    }

    const int mw = (wid & 3) * 32;
    const int nw = (wid >> 2) * 32;
    uint32_t Ab[2], Bb[2];
    make_bases(smem_u32(sA), smem_u32(sX), mw, nw, lane, Ab, Bb);

    float acc[2][4][4];
#pragma unroll
    for (int mi = 0; mi < 2; ++mi)
#pragma unroll
        for (int nj = 0; nj < 4; ++nj)
#pragma unroll
            for (int q = 0; q < 4; ++q) acc[mi][nj][q] = 0.f;

    const int i0 = blockIdx.x * TM;
    const int kBeg = blockIdx.y * KSLICE_G;

    for (int t = 0; t < NT_G; ++t) {
        const int k0 = kBeg + t * BK;
        __syncthreads();                       // previous tile fully consumed
        dequant_tile(walks, HDIM, i0, k0, sLut, sA, tid);
        xload_tile(xsrc, HDIM, k0, sX, tid);
        __syncthreads();
        tile_mma(Ab, Bb, acc);
    }

    float* part = (z ? d_upart : d_gpart) + (size_t)blockIdx.y * ((size_t)IDIM * BSZ);
    store_parts(part, i0, mw, nw, lane, acc);
}

// ---------------- reduce gate/up partials + silu*mul -> fp16 hidden ----------------
__global__ void hd_kernel(const float* __restrict__ gsl,
                          const float* __restrict__ usl,
                          const float* __restrict__ dsr) {
    int t = blockIdx.x * blockDim.x + threadIdx.x;   // IDIM*16 threads
    int i = t >> 4;
    int bq = (t & 15) * 4;
    size_t off = (size_t)i * BSZ + bq;

    float4 g = {0.f, 0.f, 0.f, 0.f}, u = {0.f, 0.f, 0.f, 0.f};
#pragma unroll
    for (int s = 0; s < SKG; ++s) {
        size_t po = (size_t)s * ((size_t)IDIM * BSZ) + off;
        float4 gv = *(const float4*)(d_gpart + po);
        float4 uv = *(const float4*)(d_upart + po);
        g.x += gv.x; g.y += gv.y; g.z += gv.z; g.w += gv.w;
        u.x += uv.x; u.y += uv.y; u.z += uv.z; u.w += uv.w;
    }
    float gl = gsl[i], ul = usl[i], dr = dsr[i];
    float gg[4] = {g.x * gl, g.y * gl, g.z * gl, g.w * gl};
    float uu[4] = {u.x * ul, u.y * ul, u.z * ul, u.w * ul};
#pragma unroll
    for (int j = 0; j < 4; ++j) {
        float sg = gg[j] / (1.0f + __expf(-gg[j]));
        d_hdh[(size_t)(bq + j) * IDIM + i] = __float2half(sg * uu[j] * dr);
    }
}

// ---------------- down GEMM ----------------
__global__ __launch_bounds__(NTHREADS, 3)
void down_kernel(const int* __restrict__ walks) {
    __shared__ __half sLut[NLUT];
    __shared__ __align__(128) char sA[TM * 128];
    __shared__ __align__(128) char sX[BSZ * 128];

    const int tid = threadIdx.x;
    const int lane = tid & 31;
    const int wid = tid >> 5;

    {
        const uint4* l4 = (const uint4*)d_ldh;
        uint4* s4 = (uint4*)sLut;
        s4[tid] = l4[tid];
        s4[tid + NTHREADS] = l4[tid + NTHREADS];
    }

    const int mw = (wid & 3) * 32;
    const int nw = (wid >> 2) * 32;
    uint32_t Ab[2], Bb[2];
    make_bases(smem_u32(sA), smem_u32(sX), mw, nw, lane, Ab, Bb);

    float acc[2][4][4];
#pragma unroll
    for (int mi = 0; mi < 2; ++mi)
#pragma unroll
        for (int nj = 0; nj < 4; ++nj)
#pragma unroll
            for (int q = 0; q < 4; ++q) acc[mi][nj][q] = 0.f;

    const int h0 = blockIdx.x * TM;
    const int kBeg = blockIdx.y * KSLICE_D;

    for (int t = 0; t < NT_D; ++t) {
        const int k0 = kBeg + t * BK;
        __syncthreads();
        dequant_tile(walks, IDIM, h0, k0, sLut, sA, tid);
        xload_tile(d_hdh, IDIM, k0, sX, tid);
        __syncthreads();
        tile_mma(Ab, Bb, acc);
    }

    float* part = d_dpart + (size_t)blockIdx.y * ((size_t)HDIM * BSZ);
    store_parts(part, h0, mw, nw, lane, acc);
}

// ---------------- reduce down partials -> out ----------------
__global__ void dreduce_kernel(const float* __restrict__ dsl, float* __restrict__ out) {
    int t = blockIdx.x * blockDim.x + threadIdx.x;   // HDIM*16 threads
    int h = t >> 4;
    int bq = (t & 15) * 4;
    size_t off = (size_t)h * BSZ + bq;

    float4 a = {0.f, 0.f, 0.f, 0.f};
#pragma unroll
    for (int s = 0; s < SKD; ++s) {
        float4 v = *(const float4*)(d_dpart + (size_t)s * ((size_t)HDIM * BSZ) + off);
        a.x += v.x; a.y += v.y; a.z += v.z; a.w += v.w;
    }
    float sc = dsl[h];
    out[(size_t)(bq + 0) * HDIM + h] = a.x * sc;
    out[(size_t)(bq + 1) * HDIM + h] = a.y * sc;
    out[(size_t)(bq + 2) * HDIM + h] = a.z * sc;
    out[(size_t)(bq + 3) * HDIM + h] = a.w * sc;
}

// ---------------- launch ----------------
extern "C" void kernel_launch(void* const* d_in, const int* in_sizes, int n_in,
                              void* d_out, int out_size) {
    const float* x        = (const float*)d_in[0];
    const float* lut_gate = (const float*)d_in[1];
    const float* lut_up   = (const float*)d_in[2];
    const float* lut_down = (const float*)d_in[3];
    const int*   gwalks   = (const int*)d_in[4];
    const int*   uwalks   = (const int*)d_in[5];
    const int*   dwalks   = (const int*)d_in[6];
    const float* gsl      = (const float*)d_in[7];
    // gsr = d_in[8]
    const float* usl      = (const float*)d_in[9];
    // usr = d_in[10]
    const float* dsl      = (const float*)d_in[11];
    const float* dsr      = (const float*)d_in[12];
    const float* gsr      = (const float*)d_in[8];
    const float* usr      = (const float*)d_in[10];
    float* out = (float*)d_out;

    prep_kernel<<<(BSZ * HDIM + 255) / 256, 256>>>(x, gsr, usr, lut_gate, lut_up, lut_down);
    gateup_kernel<<<dim3(IDIM / TM, SKG, 2), NTHREADS>>>(gwalks, uwalks);
    hd_kernel<<<(IDIM * 16) / 256, 256>>>(gsl, usl, dsr);
    down_kernel<<<dim3(HDIM / TM, SKD), NTHREADS>>>(dwalks);
    dreduce_kernel<<<(HDIM * 16) / 256, 256>>>(dsl, out);
}